// round 14
// baseline (speedup 1.0000x reference)
#include <cuda_runtime.h>
#include <cstdint>
#include <math.h>

#define NN 128
#define MM 64
#define BMAX 4096

// Scratch: beta-scaled cosine scores (2 MB) + per-batch completion counters.
__device__ float    g_z[BMAX * NN];
__device__ unsigned g_cnt[BMAX];

__device__ __forceinline__ float softplus_f(float x) {
    return x > 0.f ? x + log1pf(expf(-x)) : log1pf(expf(x));
}

__device__ __forceinline__ float warp_sum(float v) {
    #pragma unroll
    for (int o = 16; o > 0; o >>= 1) v += __shfl_xor_sync(0xffffffffu, v, o);
    return v;
}

// acq_rel atomic add, gpu scope: releases my prior stores, acquires for my
// subsequent loads. No CCTL.IVALL (unlike __threadfence).
__device__ __forceinline__ unsigned atom_add_acqrel(unsigned* p, unsigned v) {
    unsigned old;
    asm volatile("atom.add.acq_rel.gpu.global.u32 %0, [%1], %2;"
                 : "=r"(old) : "l"(p), "r"(v) : "memory");
    return old;
}

// L2-read (bypass L1) of a float4 — sees peer warp's STGs after acquire.
__device__ __forceinline__ float4 ldcg4(const float4* p) {
    float4 v;
    asm volatile("ld.global.cg.v4.f32 {%0,%1,%2,%3}, [%4];"
                 : "=f"(v.x), "=f"(v.y), "=f"(v.z), "=f"(v.w)
                 : "l"(p) : "memory");
    return v;
}

// ============================================================
// Fused: proven pure stream (one warp per half-batch) + cheap
// acq_rel handoff; second finisher runs warp-level epilogue.
// ============================================================
__global__ __launch_bounds__(256) void rom_kernel(
    const float* __restrict__ memory,   // [B, N, M]
    const float* __restrict__ key,      // [B, M]
    const float* __restrict__ beta_in,  // [B, 1]
    const float* __restrict__ g_in,     // [B, 1]
    const float* __restrict__ s_in,     // [B, 3]
    const float* __restrict__ gamma_in, // [B, 1]
    const float* __restrict__ w_prev,   // [B, N]
    float* __restrict__ out)            // [B, N]
{
    const int tid  = threadIdx.x;
    const int lane = tid & 31;
    const int task = blockIdx.x * 8 + (tid >> 5);   // warp-task id
    const int bb   = task >> 1;                     // batch
    const int h    = task & 1;                      // half (rows h*64..h*64+63)
    const int ll   = lane & 7;                      // lane within row group
    const int g    = lane >> 3;                     // row group 0..3

    // ---- Prologue: ALL epilogue-independent inputs issued up front,
    //      overlapped with the stream. ----
    const float4 wp4 = *reinterpret_cast<const float4*>(
        w_prev + (size_t)bb * NN + 4 * lane);
    const float graw = __ldg(g_in + bb);
    const float s0r  = __ldg(s_in + bb * 3 + 0);
    const float s1r  = __ldg(s_in + bb * 3 + 1);
    const float s2r  = __ldg(s_in + bb * 3 + 2);
    const float gmr  = __ldg(gamma_in + bb);

    const float4* key4 = reinterpret_cast<const float4*>(key + (size_t)bb * MM);
    const float4 k0 = __ldg(key4 + ll);
    const float4 k1 = __ldg(key4 + ll + 8);

    float kn = k0.x * k0.x + k0.y * k0.y + k0.z * k0.z + k0.w * k0.w
             + k1.x * k1.x + k1.y * k1.y + k1.z * k1.z + k1.w * k1.w;
    #pragma unroll
    for (int o = 4; o > 0; o >>= 1) kn += __shfl_xor_sync(0xffffffffu, kn, o);

    const float beta = softplus_f(__ldg(beta_in + bb));
    const float bk   = beta / fmaxf(sqrtf(kn), 1e-8f);   // beta / key_norm

    const float4* base = reinterpret_cast<const float4*>(memory)
                       + (size_t)bb * (NN * MM / 4) + (h * 64) * 16;
    float* zout = g_z + (size_t)bb * NN + h * 64;

    // ---- Stream: 16 passes of 4 rows, batched 8-deep LDG.128 (proven) ----
    #pragma unroll
    for (int blk = 0; blk < 4; ++blk) {
        float4 va[8];
        #pragma unroll
        for (int u = 0; u < 4; ++u) {
            const int row = (blk * 4 + u) * 4 + g;
            va[2 * u]     = __ldcs(base + row * 16 + ll);
            va[2 * u + 1] = __ldcs(base + row * 16 + ll + 8);
        }
        #pragma unroll
        for (int u = 0; u < 4; ++u) {
            const int row = (blk * 4 + u) * 4 + g;
            float4 v0 = va[2 * u], v1 = va[2 * u + 1];
            float dp = v0.x * k0.x + v0.y * k0.y + v0.z * k0.z + v0.w * k0.w
                     + v1.x * k1.x + v1.y * k1.y + v1.z * k1.z + v1.w * k1.w;
            float np = v0.x * v0.x + v0.y * v0.y + v0.z * v0.z + v0.w * v0.w
                     + v1.x * v1.x + v1.y * v1.y + v1.z * v1.z + v1.w * v1.w;

            // Fused 8-lane reduce: lanes ll<4 total dp, ll>=4 total np.
            float send = (lane & 4) ? dp : np;
            float recv = __shfl_xor_sync(0xffffffffu, send, 4);
            float v = ((lane & 4) ? np : dp) + recv;
            v += __shfl_xor_sync(0xffffffffu, v, 2);
            v += __shfl_xor_sync(0xffffffffu, v, 1);
            float other = __shfl_xor_sync(0xffffffffu, v, 4); // ll==0: np

            if (ll == 0) {
                float mn = fmaxf(sqrtf(other), 1e-8f);
                zout[row] = (v / mn) * bk;
            }
        }
    }

    // ---- Handoff: acq_rel atomic (no L1 flush). Second finisher runs
    //      the epilogue; first finisher exits. ----
    unsigned old = 0;
    if (lane == 0) old = atom_add_acqrel(&g_cnt[bb], 1u);
    old = __shfl_sync(0xffffffffu, old, 0);
    if (old != 1u) return;

    // ---- Warp-level epilogue: lane owns rows 4*lane..4*lane+3.
    //      z4 read via .cg (L2) — peer half's STGs are visible there. ----
    const float4 z4 = ldcg4(reinterpret_cast<const float4*>(
        g_z + (size_t)bb * NN + 4 * lane));

    const float gg = 1.f / (1.f + __expf(-graw));
    const float smax = fmaxf(s0r, fmaxf(s1r, s2r));
    const float e0 = __expf(s0r - smax), e1 = __expf(s1r - smax),
                e2 = __expf(s2r - smax);
    const float sinv = 1.f / (e0 + e1 + e2);
    const float t0 = e0 * sinv, t1 = e1 * sinv, t2 = e2 * sinv;
    const float gamma = 1.f + softplus_f(gmr);

    // softmax without max-subtraction: |z| <= beta (cos in [-1,1]), safe
    const float ex0 = __expf(z4.x), ex1 = __expf(z4.y),
                ex2 = __expf(z4.z), ex3 = __expf(z4.w);
    const float tot = warp_sum((ex0 + ex1) + (ex2 + ex3));
    const float itot = 1.f / tot;

    const float wg0 = gg * (ex0 * itot) + (1.f - gg) * wp4.x;
    const float wg1 = gg * (ex1 * itot) + (1.f - gg) * wp4.y;
    const float wg2 = gg * (ex2 * itot) + (1.f - gg) * wp4.z;
    const float wg3 = gg * (ex3 * itot) + (1.f - gg) * wp4.w;

    // circular neighbors: prev = wg3 of lane-1 (wrap), next = wg0 of lane+1
    const float prev = __shfl_sync(0xffffffffu, wg3, (lane + 31) & 31);
    const float next = __shfl_sync(0xffffffffu, wg0, (lane + 1) & 31);

    const float wh0 = prev * t0 + wg0 * t1 + wg1 * t2;
    const float wh1 = wg0  * t0 + wg1 * t1 + wg2 * t2;
    const float wh2 = wg1  * t0 + wg2 * t1 + wg3 * t2;
    const float wh3 = wg2  * t0 + wg3 * t1 + next * t2;

    const float w0 = __powf(wh0, gamma);
    const float w1 = __powf(wh1, gamma);
    const float w2 = __powf(wh2, gamma);
    const float w3 = __powf(wh3, gamma);

    const float tw = warp_sum((w0 + w1) + (w2 + w3)) + 1e-16f;
    const float itw = 1.f / tw;

    float4 o4 = make_float4(w0 * itw, w1 * itw, w2 * itw, w3 * itw);
    *reinterpret_cast<float4*>(out + (size_t)bb * NN + 4 * lane) = o4;
}

extern "C" void kernel_launch(void* const* d_in, const int* in_sizes, int n_in,
                              void* d_out, int out_size) {
    const float* memory  = (const float*)d_in[0];  // [B, N, M]
    const float* k       = (const float*)d_in[1];  // [B, M]
    const float* beta    = (const float*)d_in[2];  // [B, 1]
    const float* g       = (const float*)d_in[3];  // [B, 1]
    const float* s       = (const float*)d_in[4];  // [B, 3]
    const float* gamma   = (const float*)d_in[5];  // [B, 1]
    const float* w_prev  = (const float*)d_in[6];  // [B, N]
    float* out = (float*)d_out;

    const int B = in_sizes[0] / (NN * MM);

    // Reset per-batch completion counters (capturable async memset).
    void* cnt_ptr = nullptr;
    cudaGetSymbolAddress(&cnt_ptr, g_cnt);
    cudaMemsetAsync(cnt_ptr, 0, (size_t)B * sizeof(unsigned));

    // 2 warp-tasks per batch, 8 warps per 256-thread CTA.
    rom_kernel<<<(B * 2) / 8, 256>>>(memory, k, beta, g, s, gamma, w_prev, out);
}

// round 15
// speedup vs baseline: 1.0685x; 1.0685x over previous
#include <cuda_runtime.h>
#include <cstdint>
#include <math.h>

#define NN 128
#define MM 64
#define BMAX 4096

// Scratch: beta-scaled cosine scores (2 MB). Static device array (no alloc).
__device__ float g_z[BMAX * NN];

__device__ __forceinline__ float softplus_f(float x) {
    return x > 0.f ? x + log1pf(expf(-x)) : log1pf(expf(x));
}

__device__ __forceinline__ float warp_sum(float v) {
    #pragma unroll
    for (int o = 16; o > 0; o >>= 1) v += __shfl_xor_sync(0xffffffffu, v, o);
    return v;
}

// ============================================================
// Kernel 1: pure stream (proven ~23.1us @ 73% DRAM).
// One warp per half-batch; no smem, no block barriers.
// Triggers PDL completion immediately so ep can begin its
// independent prologue while we stream.
// ============================================================
__global__ __launch_bounds__(256) void sim_kernel(
    const float* __restrict__ memory,   // [B, N, M]
    const float* __restrict__ key,      // [B, M]
    const float* __restrict__ beta_in)  // [B, 1]
{
    cudaTriggerProgrammaticLaunchCompletion();

    const int tid  = threadIdx.x;
    const int lane = tid & 31;
    const int task = blockIdx.x * 8 + (tid >> 5);   // warp-task id
    const int bb   = task >> 1;                     // batch
    const int h    = task & 1;                      // half (rows h*64..h*64+63)
    const int ll   = lane & 7;                      // lane within row group
    const int g    = lane >> 3;                     // row group 0..3

    const float4* key4 = reinterpret_cast<const float4*>(key + (size_t)bb * MM);
    const float4 k0 = __ldg(key4 + ll);
    const float4 k1 = __ldg(key4 + ll + 8);

    float kn = k0.x * k0.x + k0.y * k0.y + k0.z * k0.z + k0.w * k0.w
             + k1.x * k1.x + k1.y * k1.y + k1.z * k1.z + k1.w * k1.w;
    #pragma unroll
    for (int o = 4; o > 0; o >>= 1) kn += __shfl_xor_sync(0xffffffffu, kn, o);

    const float beta = softplus_f(__ldg(beta_in + bb));
    const float bk   = beta / fmaxf(sqrtf(kn), 1e-8f);   // beta / key_norm

    const float4* base = reinterpret_cast<const float4*>(memory)
                       + (size_t)bb * (NN * MM / 4) + (h * 64) * 16;
    float* zout = g_z + (size_t)bb * NN + h * 64;

    #pragma unroll
    for (int blk = 0; blk < 4; ++blk) {
        float4 va[8];
        #pragma unroll
        for (int u = 0; u < 4; ++u) {
            const int row = (blk * 4 + u) * 4 + g;
            va[2 * u]     = __ldcs(base + row * 16 + ll);
            va[2 * u + 1] = __ldcs(base + row * 16 + ll + 8);
        }
        #pragma unroll
        for (int u = 0; u < 4; ++u) {
            const int row = (blk * 4 + u) * 4 + g;
            float4 v0 = va[2 * u], v1 = va[2 * u + 1];
            float dp = v0.x * k0.x + v0.y * k0.y + v0.z * k0.z + v0.w * k0.w
                     + v1.x * k1.x + v1.y * k1.y + v1.z * k1.z + v1.w * k1.w;
            float np = v0.x * v0.x + v0.y * v0.y + v0.z * v0.z + v0.w * v0.w
                     + v1.x * v1.x + v1.y * v1.y + v1.z * v1.z + v1.w * v1.w;

            // Fused 8-lane reduce: lanes ll<4 total dp, ll>=4 total np.
            float send = (lane & 4) ? dp : np;
            float recv = __shfl_xor_sync(0xffffffffu, send, 4);
            float v = ((lane & 4) ? np : dp) + recv;
            v += __shfl_xor_sync(0xffffffffu, v, 2);
            v += __shfl_xor_sync(0xffffffffu, v, 1);
            float other = __shfl_xor_sync(0xffffffffu, v, 4); // ll==0: np

            if (ll == 0) {
                float mn = fmaxf(sqrtf(other), 1e-8f);
                zout[row] = (v / mn) * bk;
            }
        }
    }
}

// ============================================================
// Kernel 2: warp-per-batch epilogue with PDL. All z-independent
// loads + math BEFORE the grid sync (overlapped with sim);
// only z-read + ~30 ops + store after.
// ============================================================
__global__ __launch_bounds__(256) void ep_kernel(
    const float* __restrict__ g_in,     // [B, 1]
    const float* __restrict__ s_in,     // [B, 3]
    const float* __restrict__ gamma_in, // [B, 1]
    const float* __restrict__ w_prev,   // [B, N]
    float* __restrict__ out)            // [B, N]
{
    const int lane = threadIdx.x & 31;
    const int bb   = blockIdx.x * 8 + (threadIdx.x >> 5);

    // ---- Pre-sync: everything that doesn't touch g_z ----
    const float4 wp4 = *reinterpret_cast<const float4*>(
        w_prev + (size_t)bb * NN + 4 * lane);
    const float graw = __ldg(g_in + bb);
    const float s0r  = __ldg(s_in + bb * 3 + 0);
    const float s1r  = __ldg(s_in + bb * 3 + 1);
    const float s2r  = __ldg(s_in + bb * 3 + 2);
    const float gmr  = __ldg(gamma_in + bb);

    const float gg = 1.f / (1.f + __expf(-graw));
    const float smax = fmaxf(s0r, fmaxf(s1r, s2r));
    const float e0 = __expf(s0r - smax), e1 = __expf(s1r - smax),
                e2 = __expf(s2r - smax);
    const float sinv = 1.f / (e0 + e1 + e2);
    const float t0 = e0 * sinv, t1 = e1 * sinv, t2 = e2 * sinv;
    const float gamma = 1.f + softplus_f(gmr);

    // ---- Wait for sim's memory to be visible ----
    cudaGridDependencySynchronize();

    const float4 z4 = *reinterpret_cast<const float4*>(
        g_z + (size_t)bb * NN + 4 * lane);

    // softmax without max-subtraction: |z| <= beta (cos in [-1,1]), safe
    const float ex0 = __expf(z4.x), ex1 = __expf(z4.y),
                ex2 = __expf(z4.z), ex3 = __expf(z4.w);
    const float tot = warp_sum((ex0 + ex1) + (ex2 + ex3));
    const float itot = 1.f / tot;

    const float wg0 = gg * (ex0 * itot) + (1.f - gg) * wp4.x;
    const float wg1 = gg * (ex1 * itot) + (1.f - gg) * wp4.y;
    const float wg2 = gg * (ex2 * itot) + (1.f - gg) * wp4.z;
    const float wg3 = gg * (ex3 * itot) + (1.f - gg) * wp4.w;

    // circular neighbors: prev = wg3 of lane-1 (wrap), next = wg0 of lane+1
    const float prev = __shfl_sync(0xffffffffu, wg3, (lane + 31) & 31);
    const float next = __shfl_sync(0xffffffffu, wg0, (lane + 1) & 31);

    const float wh0 = prev * t0 + wg0 * t1 + wg1 * t2;
    const float wh1 = wg0  * t0 + wg1 * t1 + wg2 * t2;
    const float wh2 = wg1  * t0 + wg2 * t1 + wg3 * t2;
    const float wh3 = wg2  * t0 + wg3 * t1 + next * t2;

    const float w0 = __powf(wh0, gamma);
    const float w1 = __powf(wh1, gamma);
    const float w2 = __powf(wh2, gamma);
    const float w3 = __powf(wh3, gamma);

    const float tw = warp_sum((w0 + w1) + (w2 + w3)) + 1e-16f;
    const float itw = 1.f / tw;

    float4 o4 = make_float4(w0 * itw, w1 * itw, w2 * itw, w3 * itw);
    *reinterpret_cast<float4*>(out + (size_t)bb * NN + 4 * lane) = o4;
}

extern "C" void kernel_launch(void* const* d_in, const int* in_sizes, int n_in,
                              void* d_out, int out_size) {
    const float* memory  = (const float*)d_in[0];  // [B, N, M]
    const float* k       = (const float*)d_in[1];  // [B, M]
    const float* beta    = (const float*)d_in[2];  // [B, 1]
    const float* g       = (const float*)d_in[3];  // [B, 1]
    const float* s       = (const float*)d_in[4];  // [B, 3]
    const float* gamma   = (const float*)d_in[5];  // [B, 1]
    const float* w_prev  = (const float*)d_in[6];  // [B, N]
    float* out = (float*)d_out;

    const int B = in_sizes[0] / (NN * MM);

    // Primary: pure stream.
    sim_kernel<<<(B * 2) / 8, 256>>>(memory, k, beta);

    // Secondary: PDL — launches while sim runs; syncs on its memory inside.
    cudaLaunchConfig_t cfg = {};
    cfg.gridDim  = dim3(B / 8);
    cfg.blockDim = dim3(256);
    cudaLaunchAttribute attr[1];
    attr[0].id = cudaLaunchAttributeProgrammaticStreamSerialization;
    attr[0].val.programmaticStreamSerializationAllowed = 1;
    cfg.attrs = attr;
    cfg.numAttrs = 1;
    cudaLaunchKernelEx(&cfg, ep_kernel, g, s, gamma, w_prev, out);
}

// round 16
// speedup vs baseline: 1.0971x; 1.0268x over previous
#include <cuda_runtime.h>
#include <cstdint>
#include <math.h>

#define NN 128
#define MM 64

__device__ __forceinline__ float softplus_f(float x) {
    return x > 0.f ? x + log1pf(expf(-x)) : log1pf(expf(x));
}

__device__ __forceinline__ float warp_sum(float v) {
    #pragma unroll
    for (int o = 16; o > 0; o >>= 1) v += __shfl_xor_sync(0xffffffffu, v, o);
    return v;
}

// ============================================================
// One CTA = 4 batches. 8 warps each stream one half-batch
// (identical to the proven 73%-DRAM sim stream, z -> smem).
// ONE barrier. Warps 0-3 then run the warp-level epilogue
// (one batch each). No inter-batch sequencing, no atomics.
// ============================================================
__global__ __launch_bounds__(256) void rom_kernel(
    const float* __restrict__ memory,   // [B, N, M]
    const float* __restrict__ key,      // [B, M]
    const float* __restrict__ beta_in,  // [B, 1]
    const float* __restrict__ g_in,     // [B, 1]
    const float* __restrict__ s_in,     // [B, 3]
    const float* __restrict__ gamma_in, // [B, 1]
    const float* __restrict__ w_prev,   // [B, N]
    float* __restrict__ out)            // [B, N]
{
    __shared__ float shz[4][NN];        // beta-scaled cosine per local batch

    const int tid  = threadIdx.x;
    const int lane = tid & 31;
    const int wid  = tid >> 5;          // 0..7
    const int lb   = wid >> 1;          // local batch 0..3
    const int h    = wid & 1;           // half (rows h*64..h*64+63)
    const int bb   = blockIdx.x * 4 + lb;
    const int ll   = lane & 7;          // lane within row group
    const int g    = lane >> 3;         // row group 0..3

    // ---- Key chunks ll and ll+8 ----
    const float4* key4 = reinterpret_cast<const float4*>(key + (size_t)bb * MM);
    const float4 k0 = __ldg(key4 + ll);
    const float4 k1 = __ldg(key4 + ll + 8);

    float kn = k0.x * k0.x + k0.y * k0.y + k0.z * k0.z + k0.w * k0.w
             + k1.x * k1.x + k1.y * k1.y + k1.z * k1.z + k1.w * k1.w;
    #pragma unroll
    for (int o = 4; o > 0; o >>= 1) kn += __shfl_xor_sync(0xffffffffu, kn, o);

    const float beta = softplus_f(__ldg(beta_in + bb));
    const float bk   = beta / fmaxf(sqrtf(kn), 1e-8f);   // beta / key_norm

    const float4* base = reinterpret_cast<const float4*>(memory)
                       + (size_t)bb * (NN * MM / 4) + (h * 64) * 16;
    float* zout = &shz[lb][h * 64];

    // ---- Stream: 16 passes of 4 rows, batched 8-deep LDG.128 (proven) ----
    #pragma unroll
    for (int blk = 0; blk < 4; ++blk) {
        float4 va[8];
        #pragma unroll
        for (int u = 0; u < 4; ++u) {
            const int row = (blk * 4 + u) * 4 + g;
            va[2 * u]     = __ldcs(base + row * 16 + ll);
            va[2 * u + 1] = __ldcs(base + row * 16 + ll + 8);
        }
        #pragma unroll
        for (int u = 0; u < 4; ++u) {
            const int row = (blk * 4 + u) * 4 + g;
            float4 v0 = va[2 * u], v1 = va[2 * u + 1];
            float dp = v0.x * k0.x + v0.y * k0.y + v0.z * k0.z + v0.w * k0.w
                     + v1.x * k1.x + v1.y * k1.y + v1.z * k1.z + v1.w * k1.w;
            float np = v0.x * v0.x + v0.y * v0.y + v0.z * v0.z + v0.w * v0.w
                     + v1.x * v1.x + v1.y * v1.y + v1.z * v1.z + v1.w * v1.w;

            // Fused 8-lane reduce: lanes ll<4 total dp, ll>=4 total np.
            float send = (lane & 4) ? dp : np;
            float recv = __shfl_xor_sync(0xffffffffu, send, 4);
            float v = ((lane & 4) ? np : dp) + recv;
            v += __shfl_xor_sync(0xffffffffu, v, 2);
            v += __shfl_xor_sync(0xffffffffu, v, 1);
            float other = __shfl_xor_sync(0xffffffffu, v, 4); // ll==0: np

            if (ll == 0) {
                float mn = fmaxf(sqrtf(other), 1e-8f);
                zout[row] = (v / mn) * bk;   // STS (smem)
            }
        }
    }

    // ---- The one barrier ----
    __syncthreads();

    // ---- Warp-level epilogue: warp wid<4 handles local batch wid.
    //      All inputs loaded here (post-barrier) to keep stream regs low.
    if (wid >= 4) return;
    const int be = blockIdx.x * 4 + wid;

    const float4 z4 = *reinterpret_cast<const float4*>(&shz[wid][4 * lane]);
    const float4 wp4 = *reinterpret_cast<const float4*>(
        w_prev + (size_t)be * NN + 4 * lane);

    const float gg = 1.f / (1.f + __expf(-__ldg(g_in + be)));
    const float s0r = __ldg(s_in + be * 3 + 0);
    const float s1r = __ldg(s_in + be * 3 + 1);
    const float s2r = __ldg(s_in + be * 3 + 2);
    const float smax = fmaxf(s0r, fmaxf(s1r, s2r));
    const float e0 = __expf(s0r - smax), e1 = __expf(s1r - smax),
                e2 = __expf(s2r - smax);
    const float sinv = 1.f / (e0 + e1 + e2);
    const float t0 = e0 * sinv, t1 = e1 * sinv, t2 = e2 * sinv;
    const float gamma = 1.f + softplus_f(__ldg(gamma_in + be));

    // softmax without max-subtraction: |z| <= beta (cos in [-1,1]), safe
    const float ex0 = __expf(z4.x), ex1 = __expf(z4.y),
                ex2 = __expf(z4.z), ex3 = __expf(z4.w);
    const float tot = warp_sum((ex0 + ex1) + (ex2 + ex3));
    const float itot = 1.f / tot;

    const float wg0 = gg * (ex0 * itot) + (1.f - gg) * wp4.x;
    const float wg1 = gg * (ex1 * itot) + (1.f - gg) * wp4.y;
    const float wg2 = gg * (ex2 * itot) + (1.f - gg) * wp4.z;
    const float wg3 = gg * (ex3 * itot) + (1.f - gg) * wp4.w;

    // circular neighbors: prev = wg3 of lane-1 (wrap), next = wg0 of lane+1
    const float prev = __shfl_sync(0xffffffffu, wg3, (lane + 31) & 31);
    const float next = __shfl_sync(0xffffffffu, wg0, (lane + 1) & 31);

    const float wh0 = prev * t0 + wg0 * t1 + wg1 * t2;
    const float wh1 = wg0  * t0 + wg1 * t1 + wg2 * t2;
    const float wh2 = wg1  * t0 + wg2 * t1 + wg3 * t2;
    const float wh3 = wg2  * t0 + wg3 * t1 + next * t2;

    const float w0 = __powf(wh0, gamma);
    const float w1 = __powf(wh1, gamma);
    const float w2 = __powf(wh2, gamma);
    const float w3 = __powf(wh3, gamma);

    const float tw = warp_sum((w0 + w1) + (w2 + w3)) + 1e-16f;
    const float itw = 1.f / tw;

    float4 o4 = make_float4(w0 * itw, w1 * itw, w2 * itw, w3 * itw);
    *reinterpret_cast<float4*>(out + (size_t)be * NN + 4 * lane) = o4;
}

extern "C" void kernel_launch(void* const* d_in, const int* in_sizes, int n_in,
                              void* d_out, int out_size) {
    const float* memory  = (const float*)d_in[0];  // [B, N, M]
    const float* k       = (const float*)d_in[1];  // [B, M]
    const float* beta    = (const float*)d_in[2];  // [B, 1]
    const float* g       = (const float*)d_in[3];  // [B, 1]
    const float* s       = (const float*)d_in[4];  // [B, 3]
    const float* gamma   = (const float*)d_in[5];  // [B, 1]
    const float* w_prev  = (const float*)d_in[6];  // [B, N]
    float* out = (float*)d_out;

    const int B = in_sizes[0] / (NN * MM);
    rom_kernel<<<B / 4, 256>>>(memory, k, beta, g, s, gamma, w_prev, out);
}